// round 6
// baseline (speedup 1.0000x reference)
#include <cuda_runtime.h>

#define HH 112
#define WW 112
#define CCH 64
#define BBATCH 32
#define TILE_H 16
#define SH_ROWS 20          // TILE_H + 4 halo rows
#define PITCH 120           // floats per shared row
#define BX 32               // lanes; lanes 0..27 own 4-col groups
#define NCG 28              // active column groups
#define BY 8
#define NTHREADS (BX*BY)    // 256

__device__ __forceinline__ float frcp(float d) {
    float r; asm("rcp.approx.f32 %0, %1;" : "=f"(r) : "f"(d)); return r;
}
__device__ __forceinline__ int iclamp(int v, int lo, int hi) {
    return v < lo ? lo : (v > hi ? hi : v);
}

__global__ __launch_bounds__(NTHREADS)
void bionorm_kernel(const float* __restrict__ x,
                    const float* __restrict__ sigma,
                    const float* __restrict__ pow_p,
                    const float* __restrict__ sum_kernel,
                    const float* __restrict__ weight,
                    const float* __restrict__ bias,
                    float* __restrict__ out)
{
    __shared__ float xp_sh[SH_ROWS][PITCH];     // xp, cols 0..111
    __shared__ float hs_sh[SH_ROWS][PITCH];     // horizontal 5-sums (cols 2..109 valid)
    __shared__ float kc_sh[25];
    __shared__ float sp_sh;
    __shared__ int   uni_sh;

    const int tx  = threadIdx.x;                // 0..31 (lane)
    const int ty  = threadIdx.y;                // 0..7  (warp id)
    const int tid = ty * BX + tx;
    const int c   = blockIdx.y;
    const int b   = blockIdx.z;
    const int h0  = blockIdx.x * TILE_H;
    const int w4  = 4 * tx;
    const bool act = (tx < NCG);

    const float p  = pow_p[c];
    const bool  sq = (p == 2.0f);

    if (tid < 25) kc_sh[tid] = sum_kernel[c * 25 + tid];
    if (tid == 0) {
        float s = sigma[c];
        sp_sh = sq ? s * s : powf(s, p);
        const float* kp = sum_kernel + c * 25;
        float k0 = kp[0];
        int u = 1;
        #pragma unroll
        for (int i = 1; i < 25; i++) u &= (kp[i] == k0);
        uni_sh = u;
    }
    // read uni flag via syncthreads below; branch is block-uniform

    const float* __restrict__ xin = x + (size_t)(b * CCH + c) * (HH * WW);
    const int wl4 = act ? w4 : WW - 4;          // safe load col for idle lanes

    // ---- Fused fill + horizontal sums. One warp = one row. ----
    #pragma unroll
    for (int r = ty; r < SH_ROWS; r += BY) {
        const int gr = iclamp(h0 - 2 + r, 0, HH - 1);
        float4 v = *(const float4*)&xin[gr * WW + wl4];
        float4 xp;
        if (sq) {
            xp.x = v.x * v.x; xp.y = v.y * v.y;
            xp.z = v.z * v.z; xp.w = v.w * v.w;
        } else {
            xp.x = powf(v.x, p); xp.y = powf(v.y, p);
            xp.z = powf(v.z, p); xp.w = powf(v.w, p);
        }
        // neighbor edge words via shuffle (garbage at lane 0 / lane 27: never read)
        float Lz = __shfl_up_sync(0xffffffffu,   xp.z, 1);
        float Lw = __shfl_up_sync(0xffffffffu,   xp.w, 1);
        float Rx = __shfl_down_sync(0xffffffffu, xp.x, 1);
        float Ry = __shfl_down_sync(0xffffffffu, xp.y, 1);
        float m = xp.x + xp.y + xp.z;
        float t = xp.w + Rx;
        float4 h;
        h.x = Lz + Lw + m;
        h.y = Lw + m + xp.w;
        h.z = m + t;
        h.w = xp.y + xp.z + t + Ry;
        if (act) {
            *(float4*)&xp_sh[r][w4] = xp;
            *(float4*)&hs_sh[r][w4] = h;
        }
    }
    __syncthreads();

    const float sp  = sp_sh;
    const float wgt = weight[c];
    const float bs  = bias[c];
    float* __restrict__ oimg = out + (size_t)(b * CCH + c) * (HH * WW);

    if (uni_sh) {
        // ============ FAST PATH: vertical 5-tap + normalize ============
        if (act) {
            const float k0 = kc_sh[0];
            const int ha  = h0 + 2 * ty;
            const int k0c = iclamp(ha,     2, HH - 3) - h0;
            const int k1c = iclamp(ha + 1, 2, HH - 3) - h0;
            float4 r0 = *(const float4*)&hs_sh[k0c + 0][w4];
            float4 r1 = *(const float4*)&hs_sh[k0c + 1][w4];
            float4 r2 = *(const float4*)&hs_sh[k0c + 2][w4];
            float4 r3 = *(const float4*)&hs_sh[k0c + 3][w4];
            float4 r4 = *(const float4*)&hs_sh[k0c + 4][w4];
            float4 r5 = *(const float4*)&hs_sh[k0c + 5][w4];

            float4 s0, s1;
            s0.x = r0.x + r1.x + r2.x + r3.x + r4.x;
            s0.y = r0.y + r1.y + r2.y + r3.y + r4.y;
            s0.z = r0.z + r1.z + r2.z + r3.z + r4.z;
            s0.w = r0.w + r1.w + r2.w + r3.w + r4.w;
            const bool adv = (k1c > k0c);
            s1.x = adv ? s0.x + r5.x - r0.x : s0.x;
            s1.y = adv ? s0.y + r5.y - r0.y : s0.y;
            s1.z = adv ? s0.z + r5.z - r0.z : s0.z;
            s1.w = adv ? s0.w + r5.w - r0.w : s0.w;

            // horizontal edge replication (conv-output clamp in w)
            if (tx == 0)       { s0.x = s0.z; s0.y = s0.z; s1.x = s1.z; s1.y = s1.z; }
            if (tx == NCG - 1) { s0.z = s0.y; s0.w = s0.y; s1.z = s1.y; s1.w = s1.y; }

            #pragma unroll
            for (int rr = 0; rr < 2; rr++) {
                const int k = 2 * ty + rr;
                const float4 sf = rr ? s1 : s0;
                float4 xp = *(const float4*)&xp_sh[k + 2][w4];
                float4 o;
                o.x = wgt * xp.x * frcp(fmaf(sf.x, k0, sp)) + bs;
                o.y = wgt * xp.y * frcp(fmaf(sf.y, k0, sp)) + bs;
                o.z = wgt * xp.z * frcp(fmaf(sf.z, k0, sp)) + bs;
                o.w = wgt * xp.w * frcp(fmaf(sf.w, k0, sp)) + bs;
                *(float4*)&oimg[(h0 + k) * WW + w4] = o;
            }
        }
    } else {
        // ============ GENERAL PATH: full 25-tap conv (fallback) ============
        if (act) {
            float res[2][4];
            #pragma unroll
            for (int rr = 0; rr < 2; rr++) {
                const int k = 2 * ty + rr;
                const int h = h0 + k;
                const int kr = iclamp(h, 2, HH - 3) - h0;
                #pragma unroll
                for (int j = 0; j < 4; j++) {
                    const int w  = w4 + j;
                    const int wc = iclamp(w, 2, WW - 3);
                    float acc = 0.0f;
                    #pragma unroll
                    for (int i = 0; i < 5; i++) {
                        const float* row = &xp_sh[kr + i][wc - 2];
                        acc = fmaf(kc_sh[i * 5 + 0], row[0], acc);
                        acc = fmaf(kc_sh[i * 5 + 1], row[1], acc);
                        acc = fmaf(kc_sh[i * 5 + 2], row[2], acc);
                        acc = fmaf(kc_sh[i * 5 + 3], row[3], acc);
                        acc = fmaf(kc_sh[i * 5 + 4], row[4], acc);
                    }
                    float xpv = xp_sh[k + 2][w];
                    res[rr][j] = wgt * xpv / (sp + acc) + bs;
                }
            }
            #pragma unroll
            for (int rr = 0; rr < 2; rr++) {
                const int h = h0 + 2 * ty + rr;
                float4 o = make_float4(res[rr][0], res[rr][1], res[rr][2], res[rr][3]);
                *(float4*)&oimg[h * WW + w4] = o;
            }
        }
    }
}

extern "C" void kernel_launch(void* const* d_in, const int* in_sizes, int n_in,
                              void* d_out, int out_size)
{
    const float* x          = (const float*)d_in[0];
    const float* sigma      = (const float*)d_in[1];
    const float* pow_p      = (const float*)d_in[2];
    const float* sum_kernel = (const float*)d_in[3];
    const float* weight     = (const float*)d_in[4];
    const float* bias       = (const float*)d_in[5];
    float* out = (float*)d_out;

    dim3 grid(HH / TILE_H, CCH, BBATCH);   // (7, 64, 32)
    dim3 block(BX, BY, 1);                 // 256 threads (28/32 lanes active)
    bionorm_kernel<<<grid, block>>>(x, sigma, pow_p, sum_kernel, weight, bias, out);
}

// round 7
// speedup vs baseline: 1.1389x; 1.1389x over previous
#include <cuda_runtime.h>

#define HH 112
#define WW 112
#define CCH 64
#define BBATCH 32
#define BANDS 8
#define BH 14             // output rows per band
#define NSTEP 18          // BH + 4 halo rows
#define BX 32             // lanes; 0..27 own 4-col groups
#define NCG 28
#define NTHREADS 256

__device__ __forceinline__ float frcp(float d) {
    float r; asm("rcp.approx.f32 %0, %1;" : "=f"(r) : "f"(d)); return r;
}
__device__ __forceinline__ int iclamp(int v, int lo, int hi) {
    return v < lo ? lo : (v > hi ? hi : v);
}

__global__ __launch_bounds__(NTHREADS, 3)
void bionorm_kernel(const float* __restrict__ x,
                    const float* __restrict__ sigma,
                    const float* __restrict__ pow_p,
                    const float* __restrict__ sum_kernel,
                    const float* __restrict__ weight,
                    const float* __restrict__ bias,
                    float* __restrict__ out)
{
    __shared__ float kc_sh[25];
    __shared__ float sp_sh;
    __shared__ int   uni_sh;

    const int tx  = threadIdx.x;             // lane: column group (0..27 active)
    const int ty  = threadIdx.y;             // band 0..7
    const int tid = ty * BX + tx;
    const int c   = blockIdx.x;
    const int b   = blockIdx.y;
    const int r0  = ty * BH;
    const int w4  = 4 * tx;
    const bool act = (tx < NCG);
    const int wl4 = act ? w4 : WW - 4;       // safe col for idle lanes

    const float p  = pow_p[c];
    const bool  sq = (p == 2.0f);

    if (tid < 25) kc_sh[tid] = sum_kernel[c * 25 + tid];
    if (tid == 0) {
        float s = sigma[c];
        sp_sh = sq ? s * s : powf(s, p);
        const float* kp = sum_kernel + c * 25;
        float k0 = kp[0];
        int u = 1;
        #pragma unroll
        for (int i = 1; i < 25; i++) u &= (kp[i] == k0);
        uni_sh = u;
    }
    __syncthreads();

    const float* __restrict__ xin  = x   + (size_t)(b * CCH + c) * (HH * WW);
    float* __restrict__       oimg = out + (size_t)(b * CCH + c) * (HH * WW);
    const float sp  = sp_sh;
    const float wgt = weight[c];
    const float bs  = bias[c];

    if (uni_sh) {
        // ========== FAST PATH: register-streaming separable box filter =====
        const float k0 = kc_sh[0];

        float4 hist[5];                      // hsum history (circular 5)
        float4 xph[3];                       // xp history (lag <= 2)
        float4 s4  = make_float4(0.f, 0.f, 0.f, 0.f);   // running 5-row sum
        float4 sft = make_float4(0.f, 0.f, 0.f, 0.f);   // sf at center 109 (ty==7)
        #pragma unroll
        for (int q = 0; q < 5; q++) hist[q] = make_float4(0.f, 0.f, 0.f, 0.f);

        #pragma unroll
        for (int i = 0; i < NSTEP; i++) {
            const int lr = iclamp(r0 - 2 + i, 0, HH - 1);
            float4 v = *(const float4*)&xin[lr * WW + wl4];
            float4 xp;
            if (sq) { xp.x = v.x*v.x; xp.y = v.y*v.y; xp.z = v.z*v.z; xp.w = v.w*v.w; }
            else    { xp.x = powf(v.x,p); xp.y = powf(v.y,p); xp.z = powf(v.z,p); xp.w = powf(v.w,p); }

            // neighbor edge words (garbage crossings land only on fixed-up cols)
            float Lz = __shfl_up_sync(0xffffffffu,   xp.z, 1);
            float Lw = __shfl_up_sync(0xffffffffu,   xp.w, 1);
            float Rx = __shfl_down_sync(0xffffffffu, xp.x, 1);
            float Ry = __shfl_down_sync(0xffffffffu, xp.y, 1);

            float m = xp.x + xp.y + xp.z;
            float t = xp.w + Rx;
            float4 h;
            h.x = Lz + Lw + m;
            h.y = Lw + m + xp.w;
            h.z = m + t;
            h.w = xp.y + xp.z + t + Ry;

            // sliding vertical 5-sum
            float4& old = hist[i % 5];
            s4.x += h.x - old.x;  s4.y += h.y - old.y;
            s4.z += h.z - old.z;  s4.w += h.w - old.w;
            old = h;
            xph[i % 3] = xp;

            if (i == 15) { if (ty == BANDS - 1) sft = s4; }   // sf(center 109)

            if (i >= 4) {
                float4 sfv = s4;
                if (i >= 16) { if (ty == BANDS - 1) sfv = sft; }   // rows 110/111
                // horizontal conv-output replication (cols 0,1 <- 2; 110,111 <- 109)
                if (tx == 0)       { sfv.x = sfv.z; sfv.y = sfv.z; }
                if (tx == NCG - 1) { sfv.z = sfv.y; sfv.w = sfv.y; }

                const float4 xpv = xph[(i - 2) % 3];
                if (act && (i >= 6 || ty != 0)) {
                    const int hrow = r0 + i - 4;
                    float4 o;
                    o.x = fmaf(wgt * xpv.x, frcp(fmaf(sfv.x, k0, sp)), bs);
                    o.y = fmaf(wgt * xpv.y, frcp(fmaf(sfv.y, k0, sp)), bs);
                    o.z = fmaf(wgt * xpv.z, frcp(fmaf(sfv.z, k0, sp)), bs);
                    o.w = fmaf(wgt * xpv.w, frcp(fmaf(sfv.w, k0, sp)), bs);
                    *(float4*)&oimg[hrow * WW + w4] = o;
                }
                // rows 0,1 replicate sf(center 2) = s4 at i==6; reload x (L1 hit)
                if (i == 6) {
                    if (ty == 0 && act) {
                        #pragma unroll
                        for (int rr = 0; rr < 2; rr++) {
                            float4 vv = *(const float4*)&xin[rr * WW + w4];
                            float4 xq;
                            if (sq) { xq.x=vv.x*vv.x; xq.y=vv.y*vv.y; xq.z=vv.z*vv.z; xq.w=vv.w*vv.w; }
                            else    { xq.x=powf(vv.x,p); xq.y=powf(vv.y,p); xq.z=powf(vv.z,p); xq.w=powf(vv.w,p); }
                            float4 o;
                            o.x = fmaf(wgt * xq.x, frcp(fmaf(sfv.x, k0, sp)), bs);
                            o.y = fmaf(wgt * xq.y, frcp(fmaf(sfv.y, k0, sp)), bs);
                            o.z = fmaf(wgt * xq.z, frcp(fmaf(sfv.z, k0, sp)), bs);
                            o.w = fmaf(wgt * xq.w, frcp(fmaf(sfv.w, k0, sp)), bs);
                            *(float4*)&oimg[rr * WW + w4] = o;
                        }
                    }
                }
            }
        }
    } else {
        // ========== GENERAL PATH: direct 25-tap from global (fallback) =====
        if (act) {
            float kc[25];
            #pragma unroll
            for (int q = 0; q < 25; q++) kc[q] = kc_sh[q];
            for (int j = 0; j < BH; j++) {
                const int hrow = r0 + j;
                const int hc = iclamp(hrow, 2, HH - 3);
                float4 o;
                float* op = &o.x;
                #pragma unroll
                for (int jj = 0; jj < 4; jj++) {
                    const int w  = w4 + jj;
                    const int wc = iclamp(w, 2, WW - 3);
                    float acc = 0.0f;
                    #pragma unroll
                    for (int ki = 0; ki < 5; ki++) {
                        const float* row = &xin[(hc + ki - 2) * WW + (wc - 2)];
                        #pragma unroll
                        for (int kj = 0; kj < 5; kj++) {
                            float xv = row[kj];
                            float xpv = sq ? xv * xv : powf(xv, p);
                            acc = fmaf(kc[ki * 5 + kj], xpv, acc);
                        }
                    }
                    float xv = xin[hrow * WW + w];
                    float xpv = sq ? xv * xv : powf(xv, p);
                    op[jj] = wgt * xpv / (sp + acc) + bs;
                }
                *(float4*)&oimg[hrow * WW + w4] = o;
            }
        }
    }
}

extern "C" void kernel_launch(void* const* d_in, const int* in_sizes, int n_in,
                              void* d_out, int out_size)
{
    const float* x          = (const float*)d_in[0];
    const float* sigma      = (const float*)d_in[1];
    const float* pow_p      = (const float*)d_in[2];
    const float* sum_kernel = (const float*)d_in[3];
    const float* weight     = (const float*)d_in[4];
    const float* bias       = (const float*)d_in[5];
    float* out = (float*)d_out;

    dim3 grid(CCH, BBATCH);        // 2048 CTAs, one per (b,c) image
    dim3 block(BX, BANDS, 1);      // 256 threads
    bionorm_kernel<<<grid, block>>>(x, sigma, pow_p, sum_kernel, weight, bias, out);
}